// round 3
// baseline (speedup 1.0000x reference)
#include <cuda_runtime.h>
#include <math.h>

#define TT 20
#define MM 2000
#define NROWS (TT*MM)          // 40000, row index = t*MM + m
#define CAP 96

// ---------------- static scratch ----------------
__device__ float          d_maskf[NROWS];
__device__ int            d_cnt[NROWS];
__device__ float          d_dinv[NROWS];
__device__ unsigned short d_nbr[(size_t)NROWS * CAP];
__device__ float          d_bufA[(size_t)NROWS * 128];   // Z1 / Z2
__device__ float          d_bufB[(size_t)NROWS * 128];   // h1 / placeholder
__device__ float          d_gpre[(size_t)NROWS * 512];   // [m*T+t][512]
__device__ float          d_lstm[(size_t)NROWS * 128];   // [m*T+t][128]

__device__ __forceinline__ float sigm(float x) { return 1.0f / (1.0f + expf(-x)); }

// ---------------- mask init ----------------
__global__ void k_init(const unsigned int* __restrict__ em) {
    int idx = blockIdx.x * 256 + threadIdx.x;
    if (idx >= NROWS) return;
    int t = idx / MM, i = idx % MM;
    int b = i / 500, n = i % 500;
    d_maskf[idx] = em[(b * TT + t) * 500 + n] ? 1.0f : 0.0f;
}

// ---------------- column-scan sparse extraction (atomic-free, deterministic) ----------------
__global__ void k_extract(const float* __restrict__ adj) {
    int t = blockIdx.y;
    int i = blockIdx.x * 256 + threadIdx.x;
    __shared__ float msm[MM];
    for (int j = threadIdx.x; j < MM; j += 256) msm[j] = d_maskf[t * MM + j];
    __syncthreads();
    if (i >= MM) return;
    const float* a = adj + (size_t)t * MM * MM + i;   // column i
    unsigned short* list = d_nbr + (size_t)(t * MM + i) * CAP;
    int cnt = 0;
    #pragma unroll 8
    for (int j = 0; j < MM; j++) {
        float av = a[(size_t)j * MM];
        if (av != 0.0f && msm[j] != 0.0f) {
            if (cnt < CAP) list[cnt] = (unsigned short)j;
            cnt++;
        }
    }
    float mi = d_maskf[t * MM + i];
    d_cnt[t * MM + i] = (cnt < CAP ? cnt : CAP);
    d_dinv[t * MM + i] = (mi != 0.0f) ? rsqrtf((float)cnt + 1.0f) : 0.0f;
}

// ---------------- Z1 = dinv .* (x @ W1) ----------------
__global__ void k_z1(const float* __restrict__ pos, const float* __restrict__ W1) {
    int idx = blockIdx.x * 256 + threadIdx.x;
    if (idx >= NROWS * 128) return;
    int row = idx >> 7, c = idx & 127;
    float x0 = __ldg(&pos[(size_t)row * 2]);
    float x1 = __ldg(&pos[(size_t)row * 2 + 1]);
    d_bufA[idx] = d_dinv[row] * (x0 * __ldg(&W1[c]) + x1 * __ldg(&W1[128 + c]));
}

// ---------------- aggregation: out[i] = f( dinv[i]*(sum_nbr Z[j] + Z[i]) + bias ) ----------------
// mode 0: relu(v + b1)        (GCN layer 1)
// mode 1: (v + b2) * mask     (GCN layer 2)
__global__ void k_agg(const float* __restrict__ Zin, const float* __restrict__ bias,
                      float* __restrict__ out, int mode) {
    int row = blockIdx.x;
    int f = threadIdx.x;
    int t = row / MM;
    size_t base = (size_t)t * MM;
    float acc = Zin[(size_t)row * 128 + f];
    int n = d_cnt[row];
    const unsigned short* lst = &d_nbr[(size_t)row * CAP];
    for (int idx = 0; idx < n; idx++) {
        int j = lst[idx];
        acc += Zin[(base + j) * 128 + f];
    }
    float v = d_dinv[row] * acc + __ldg(&bias[f]);
    if (mode == 0) out[(size_t)row * 128 + f] = fmaxf(v, 0.0f);
    else           out[(size_t)row * 128 + f] = v * d_maskf[row];
}

// ---------------- tiled GEMM, K=128 fixed ----------------
// C[r][c0+c] = sum_k Atile[r][k] * Bs[c][k]  (+ epilogue)
// mode 0 (Z2):    A row = r,                B = W2   [k][c],  epi: *dinv[r]
// mode 1 (gates): A row = (r%20)*2000+r/20, B = W_ih [c][k],  epi: + b_ih[c]+b_hh[c]
__global__ void __launch_bounds__(256)
k_gemm(const float* __restrict__ A, const float* __restrict__ B, float* __restrict__ C,
       const float* __restrict__ bia, const float* __restrict__ bib,
       int mode, int ncols) {
    extern __shared__ float sm[];
    float* As = sm;            // [64][128]
    float* Bs = sm + 64 * 128; // [128][129]
    int r0 = blockIdx.x * 64, c0 = blockIdx.y * 128;
    int tid = threadIdx.x;

    for (int i = tid; i < 64 * 32; i += 256) {
        int row = i / 32, k4 = i % 32;
        int gr = r0 + row;
        int arow = (mode == 1) ? ((gr % TT) * MM + gr / TT) : gr;
        ((float4*)As)[row * 32 + k4] = ((const float4*)A)[(size_t)arow * 32 + k4];
    }
    if (mode == 1) {  // B = W_ih, layout [c][k]
        for (int i = tid; i < 128 * 32; i += 256) {
            int c = i / 32, k4 = i % 32;
            float4 v = ((const float4*)B)[(size_t)(c0 + c) * 32 + k4];
            Bs[c * 129 + 4 * k4 + 0] = v.x; Bs[c * 129 + 4 * k4 + 1] = v.y;
            Bs[c * 129 + 4 * k4 + 2] = v.z; Bs[c * 129 + 4 * k4 + 3] = v.w;
        }
    } else {          // B = W2, layout [k][c] -> transpose into Bs[c][k]
        for (int i = tid; i < 128 * 32; i += 256) {
            int k = i / 32, c4 = i % 32;
            float4 v = ((const float4*)B)[(size_t)k * 32 + c4];
            Bs[(4 * c4 + 0) * 129 + k] = v.x; Bs[(4 * c4 + 1) * 129 + k] = v.y;
            Bs[(4 * c4 + 2) * 129 + k] = v.z; Bs[(4 * c4 + 3) * 129 + k] = v.w;
        }
    }
    __syncthreads();

    int tx = tid % 32, ty = tid / 32;   // rows ty*8..+7 ; cols tx+32*cc
    float acc[8][4];
    #pragma unroll
    for (int rr = 0; rr < 8; rr++)
        #pragma unroll
        for (int cc = 0; cc < 4; cc++) acc[rr][cc] = 0.0f;

    const float4* As4 = (const float4*)As;
    #pragma unroll
    for (int k4 = 0; k4 < 32; k4++) {
        float4 a4[8];
        #pragma unroll
        for (int rr = 0; rr < 8; rr++) a4[rr] = As4[(ty * 8 + rr) * 32 + k4];
        #pragma unroll
        for (int cc = 0; cc < 4; cc++) {
            int c = tx + 32 * cc;
            float b0 = Bs[c * 129 + 4 * k4 + 0];
            float b1 = Bs[c * 129 + 4 * k4 + 1];
            float b2 = Bs[c * 129 + 4 * k4 + 2];
            float b3 = Bs[c * 129 + 4 * k4 + 3];
            #pragma unroll
            for (int rr = 0; rr < 8; rr++)
                acc[rr][cc] += a4[rr].x * b0 + a4[rr].y * b1 + a4[rr].z * b2 + a4[rr].w * b3;
        }
    }
    #pragma unroll
    for (int cc = 0; cc < 4; cc++) {
        int c = tx + 32 * cc;
        float bv = (mode == 1) ? (__ldg(&bia[c0 + c]) + __ldg(&bib[c0 + c])) : 0.0f;
        #pragma unroll
        for (int rr = 0; rr < 8; rr++) {
            int r = r0 + ty * 8 + rr;
            float v = acc[rr][cc];
            if (mode == 1) v += bv;
            else           v *= d_dinv[r];
            C[(size_t)r * ncols + c0 + c] = v;
        }
    }
}

// ---------------- persistent LSTM: 20 blocks (one per t-row), 512 threads (one per gate) ----------------
__global__ void __launch_bounds__(512, 1)
k_lstm(const float* __restrict__ Whh) {
    extern __shared__ float sm[];
    float4* Wsm4 = (float4*)sm;            // [16][512] : W_hh[g][64+4kb..+3]
    float* hsm = sm + 16 * 512 * 4;        // 128
    float* gsm = hsm + 128;                // 512
    int t = blockIdx.x, g = threadIdx.x;

    float w[64];
    #pragma unroll
    for (int kb = 0; kb < 16; kb++) {
        float4 v = __ldg((const float4*)&Whh[(size_t)g * 128 + 4 * kb]);
        w[4 * kb] = v.x; w[4 * kb + 1] = v.y; w[4 * kb + 2] = v.z; w[4 * kb + 3] = v.w;
    }
    #pragma unroll
    for (int kb = 0; kb < 16; kb++)
        Wsm4[kb * 512 + g] = __ldg((const float4*)&Whh[(size_t)g * 128 + 64 + 4 * kb]);

    float c = 0.0f;
    if (g < 128) hsm[g] = 0.0f;
    __syncthreads();

    float nextg = d_gpre[(size_t)t * 512 + g];   // m = 0
    for (int m = 0; m < MM; m++) {
        float acc = nextg;
        if (m < MM - 1) nextg = d_gpre[(size_t)((m + 1) * TT + t) * 512 + g];
        const float4* h4 = (const float4*)hsm;
        #pragma unroll
        for (int kb = 0; kb < 16; kb++) {
            float4 hv = h4[kb];
            acc += hv.x * w[4 * kb] + hv.y * w[4 * kb + 1] + hv.z * w[4 * kb + 2] + hv.w * w[4 * kb + 3];
        }
        #pragma unroll
        for (int kb = 0; kb < 16; kb++) {
            float4 hv = h4[16 + kb];
            float4 wv = Wsm4[kb * 512 + g];
            acc += hv.x * wv.x + hv.y * wv.y + hv.z * wv.z + hv.w * wv.w;
        }
        gsm[g] = acc;
        __syncthreads();
        if (g < 128) {
            float ig = sigm(gsm[g]);
            float fg = sigm(gsm[128 + g]);
            float gg = tanhf(gsm[256 + g]);
            float og = sigm(gsm[384 + g]);
            c = fg * c + ig * gg;
            float hn = og * tanhf(c);
            hsm[g] = hn;
            d_lstm[(size_t)(m * TT + t) * 128 + g] = hn;
        }
        __syncthreads();
    }
}

// ---------------- fused FC1(relu)+FC2 ----------------
__global__ void __launch_bounds__(256)
k_fc(const float* __restrict__ fc1w, const float* __restrict__ fc1b,
     const float* __restrict__ fc2w, const float* __restrict__ fc2b,
     float* __restrict__ out) {
    __shared__ float w1s[128 * 64], w2s[64 * 32], xs[4 * 128], mid[4 * 64], b1s[64], b2s[32];
    int tid = threadIdx.x;
    for (int i = tid; i < 8192; i += 256) w1s[i] = fc1w[i];
    for (int i = tid; i < 2048; i += 256) w2s[i] = fc2w[i];
    if (tid < 64) b1s[tid] = fc1b[tid];
    if (tid < 32) b2s[tid] = fc2b[tid];
    __syncthreads();
    int rbase = blockIdx.x * 64;
    for (int chunk = 0; chunk < 16; chunk++) {
        int r0 = rbase + chunk * 4;
        for (int i = tid; i < 512; i += 256)
            xs[i] = d_lstm[(size_t)(r0 + i / 128) * 128 + (i & 127)];
        __syncthreads();
        {
            int r = tid / 64, cc = tid % 64;
            float acc = b1s[cc];
            #pragma unroll 8
            for (int k = 0; k < 128; k++) acc += xs[r * 128 + k] * w1s[k * 64 + cc];
            mid[r * 64 + cc] = fmaxf(acc, 0.0f);
        }
        __syncthreads();
        if (tid < 128) {
            int r = tid / 32, o = tid % 32;
            float acc = b2s[o];
            #pragma unroll 8
            for (int k = 0; k < 64; k++) acc += mid[r * 64 + k] * w2s[k * 32 + o];
            out[(size_t)(r0 + r) * 32 + o] = acc;
        }
        __syncthreads();
    }
}

// ---------------- launch ----------------
extern "C" void kernel_launch(void* const* d_in, const int* in_sizes, int n_in,
                              void* d_out, int out_size) {
    const float* positions = (const float*)d_in[0];
    const float* adjacency = (const float*)d_in[1];
    const unsigned int* ego = (const unsigned int*)d_in[2];
    const float* W1   = (const float*)d_in[3];
    const float* b1   = (const float*)d_in[4];
    const float* W2   = (const float*)d_in[5];
    const float* b2   = (const float*)d_in[6];
    const float* W_ih = (const float*)d_in[7];
    const float* W_hh = (const float*)d_in[8];
    const float* b_ih = (const float*)d_in[9];
    const float* b_hh = (const float*)d_in[10];
    const float* fc1w = (const float*)d_in[11];
    const float* fc1b = (const float*)d_in[12];
    const float* fc2w = (const float*)d_in[13];
    const float* fc2b = (const float*)d_in[14];
    float* out = (float*)d_out;

    static const int GEMM_SMEM = (64 * 128 + 128 * 129) * 4;        // 98816
    static const int LSTM_SMEM = (16 * 512 * 4 + 128 + 512) * 4;    // 133632
    cudaFuncSetAttribute(k_gemm, cudaFuncAttributeMaxDynamicSharedMemorySize, GEMM_SMEM);
    cudaFuncSetAttribute(k_lstm, cudaFuncAttributeMaxDynamicSharedMemorySize, LSTM_SMEM);

    float* bufA; cudaGetSymbolAddress((void**)&bufA, d_bufA);
    float* bufB; cudaGetSymbolAddress((void**)&bufB, d_bufB);
    float* gpre; cudaGetSymbolAddress((void**)&gpre, d_gpre);

    k_init<<<(NROWS + 255) / 256, 256>>>(ego);
    k_extract<<<dim3(8, TT), 256>>>(adjacency);
    k_z1<<<(NROWS * 128 + 255) / 256, 256>>>(positions, W1);
    k_agg<<<NROWS, 128>>>(bufA, b1, bufB, 0);                       // h1
    k_gemm<<<dim3(625, 1), 256, GEMM_SMEM>>>(bufB, W2, bufA, 0, 0, 0, 128);   // Z2
    k_agg<<<NROWS, 128>>>(bufA, b2, bufB, 1);                       // placeholder
    k_gemm<<<dim3(625, 4), 256, GEMM_SMEM>>>(bufB, W_ih, gpre, b_ih, b_hh, 1, 512);
    k_lstm<<<TT, 512, LSTM_SMEM>>>(W_hh);
    k_fc<<<625, 256>>>(fc1w, fc1b, fc2w, fc2b, out);
}

// round 4
// speedup vs baseline: 1.2950x; 1.2950x over previous
#include <cuda_runtime.h>
#include <math.h>

#define TT 20
#define MM 2000
#define NROWS (TT*MM)          // 40000, row index = t*MM + m
#define CAP 96

#define FMA2(d,a,b) asm("fma.rn.f32x2 %0,%1,%2,%0;" : "+l"(d) : "l"(a), "l"(b))
#define UNPK(lo,hi,v) asm("mov.b64 {%0,%1},%2;" : "=f"(lo), "=f"(hi) : "l"(v))

// ---------------- static scratch ----------------
__device__ float          d_maskf[NROWS];
__device__ int            d_cnt[NROWS];
__device__ float          d_dinv[NROWS];
__device__ unsigned short d_nbr[(size_t)NROWS * CAP];
__device__ float          d_bufA[(size_t)NROWS * 128];   // Z1 / Z2
__device__ float          d_bufB[(size_t)NROWS * 128];   // h1 / placeholder
__device__ float          d_gpre[(size_t)NROWS * 512];   // [m*T+t][512]
__device__ float          d_lstm[(size_t)NROWS * 128];   // [m*T+t][128]

__device__ __forceinline__ float sigm(float x) { return 1.0f / (1.0f + expf(-x)); }

// ---------------- mask init ----------------
__global__ void k_init(const unsigned int* __restrict__ em) {
    int idx = blockIdx.x * 256 + threadIdx.x;
    if (idx >= NROWS) return;
    int t = idx / MM, i = idx % MM;
    int b = i / 500, n = i % 500;
    d_maskf[idx] = em[(b * TT + t) * 500 + n] ? 1.0f : 0.0f;
}

// ---------------- column-scan sparse extraction (atomic-free, deterministic) ----------------
__global__ void k_extract(const float* __restrict__ adj) {
    int t = blockIdx.y;
    int i = blockIdx.x * 256 + threadIdx.x;
    __shared__ float msm[MM];
    for (int j = threadIdx.x; j < MM; j += 256) msm[j] = d_maskf[t * MM + j];
    __syncthreads();
    if (i >= MM) return;
    const float* a = adj + (size_t)t * MM * MM + i;   // column i
    unsigned short* list = d_nbr + (size_t)(t * MM + i) * CAP;
    int cnt = 0;
    #pragma unroll 8
    for (int j = 0; j < MM; j++) {
        float av = a[(size_t)j * MM];
        if (av != 0.0f && msm[j] != 0.0f) {
            if (cnt < CAP) list[cnt] = (unsigned short)j;
            cnt++;
        }
    }
    float mi = d_maskf[t * MM + i];
    d_cnt[t * MM + i] = (cnt < CAP ? cnt : CAP);
    d_dinv[t * MM + i] = (mi != 0.0f) ? rsqrtf((float)cnt + 1.0f) : 0.0f;
}

// ---------------- Z1 = dinv .* (x @ W1) ----------------
__global__ void k_z1(const float* __restrict__ pos, const float* __restrict__ W1) {
    int idx = blockIdx.x * 256 + threadIdx.x;
    if (idx >= NROWS * 128) return;
    int row = idx >> 7, c = idx & 127;
    float x0 = __ldg(&pos[(size_t)row * 2]);
    float x1 = __ldg(&pos[(size_t)row * 2 + 1]);
    d_bufA[idx] = d_dinv[row] * (x0 * __ldg(&W1[c]) + x1 * __ldg(&W1[128 + c]));
}

// ---------------- aggregation: out[i] = f( dinv[i]*(sum_nbr Z[j] + Z[i]) + bias ) ----------------
__global__ void k_agg(const float* __restrict__ Zin, const float* __restrict__ bias,
                      float* __restrict__ out, int mode) {
    int row = blockIdx.x;
    int f = threadIdx.x;
    int t = row / MM;
    size_t base = (size_t)t * MM;
    float acc = Zin[(size_t)row * 128 + f];
    int n = d_cnt[row];
    const unsigned short* lst = &d_nbr[(size_t)row * CAP];
    for (int idx = 0; idx < n; idx++) {
        int j = lst[idx];
        acc += Zin[(base + j) * 128 + f];
    }
    float v = d_dinv[row] * acc + __ldg(&bias[f]);
    if (mode == 0) out[(size_t)row * 128 + f] = fmaxf(v, 0.0f);
    else           out[(size_t)row * 128 + f] = v * d_maskf[row];
}

// ---------------- tiled GEMM, K=128 fixed, packed f32x2 ----------------
// mode 0 (Z2):    A row = r,                B = W2   [k][c],  epi: *dinv[r]
// mode 1 (gates): A row = (r%20)*2000+r/20, B = W_ih [c][k],  epi: + b_ih[c]+b_hh[c]
__global__ void __launch_bounds__(256)
k_gemm(const float* __restrict__ A, const float* __restrict__ B, float* __restrict__ C,
       const float* __restrict__ bia, const float* __restrict__ bib,
       int mode, int ncols) {
    extern __shared__ float sm[];
    float* As = sm;            // [64][128]
    float* Bs = sm + 64 * 128; // [128][130]  (even pad -> 8B-aligned k-pairs)
    int r0 = blockIdx.x * 64, c0 = blockIdx.y * 128;
    int tid = threadIdx.x;

    for (int i = tid; i < 64 * 32; i += 256) {
        int row = i / 32, k4 = i % 32;
        int gr = r0 + row;
        int arow = (mode == 1) ? ((gr % TT) * MM + gr / TT) : gr;
        ((float4*)As)[row * 32 + k4] = ((const float4*)A)[(size_t)arow * 32 + k4];
    }
    if (mode == 1) {  // B = W_ih, layout [c][k]
        for (int i = tid; i < 128 * 32; i += 256) {
            int c = i / 32, k4 = i % 32;
            float4 v = ((const float4*)B)[(size_t)(c0 + c) * 32 + k4];
            Bs[c * 130 + 4 * k4 + 0] = v.x; Bs[c * 130 + 4 * k4 + 1] = v.y;
            Bs[c * 130 + 4 * k4 + 2] = v.z; Bs[c * 130 + 4 * k4 + 3] = v.w;
        }
    } else {          // B = W2, layout [k][c] -> transpose into Bs[c][k]
        for (int i = tid; i < 128 * 32; i += 256) {
            int k = i / 32, c4 = i % 32;
            float4 v = ((const float4*)B)[(size_t)k * 32 + c4];
            Bs[(4 * c4 + 0) * 130 + k] = v.x; Bs[(4 * c4 + 1) * 130 + k] = v.y;
            Bs[(4 * c4 + 2) * 130 + k] = v.z; Bs[(4 * c4 + 3) * 130 + k] = v.w;
        }
    }
    __syncthreads();

    int tx = tid % 32, ty = tid / 32;   // rows ty*8..+7 ; cols tx+32*cc
    unsigned long long acc[8][4];
    #pragma unroll
    for (int rr = 0; rr < 8; rr++)
        #pragma unroll
        for (int cc = 0; cc < 4; cc++) acc[rr][cc] = 0ull;

    const ulonglong2* As2 = (const ulonglong2*)As;   // [64][32] of 16B
    #pragma unroll 4
    for (int k4 = 0; k4 < 32; k4++) {
        ulonglong2 a[8];
        #pragma unroll
        for (int rr = 0; rr < 8; rr++) a[rr] = As2[(ty * 8 + rr) * 32 + k4];
        #pragma unroll
        for (int cc = 0; cc < 4; cc++) {
            int c = tx + 32 * cc;
            const unsigned long long* bp = (const unsigned long long*)(Bs + c * 130 + 4 * k4);
            unsigned long long b0 = bp[0], b1 = bp[1];
            #pragma unroll
            for (int rr = 0; rr < 8; rr++) {
                FMA2(acc[rr][cc], a[rr].x, b0);
                FMA2(acc[rr][cc], a[rr].y, b1);
            }
        }
    }
    #pragma unroll
    for (int cc = 0; cc < 4; cc++) {
        int c = tx + 32 * cc;
        float bv = (mode == 1) ? (__ldg(&bia[c0 + c]) + __ldg(&bib[c0 + c])) : 0.0f;
        #pragma unroll
        for (int rr = 0; rr < 8; rr++) {
            int r = r0 + ty * 8 + rr;
            float lo, hi; UNPK(lo, hi, acc[rr][cc]);
            float v = lo + hi;
            if (mode == 1) v += bv;
            else           v *= d_dinv[r];
            C[(size_t)r * ncols + c0 + c] = v;
        }
    }
}

// ---------------- persistent LSTM: 20 blocks, 512 threads (1 gate/thread) ----------------
// W_hh[g][0:96) in 48 packed-ull registers, [96:128) in smem; all math packed f32x2.
__global__ void __launch_bounds__(512, 1)
k_lstm(const float* __restrict__ Whh) {
    extern __shared__ float sm[];
    float* Wq  = sm;                 // [8][512] float4 : W_hh[g][96+4kq .. +3]
    float* hsm = sm + 8 * 512 * 4;   // 128
    float* gsm = hsm + 128;          // 512
    int t = blockIdx.x, g = threadIdx.x;

    unsigned long long w[48];
    const unsigned long long* wrow = (const unsigned long long*)(Whh + (size_t)g * 128);
    #pragma unroll
    for (int i = 0; i < 48; i++) w[i] = wrow[i];
    #pragma unroll
    for (int kq = 0; kq < 8; kq++)
        ((float4*)Wq)[kq * 512 + g] = __ldg((const float4*)(Whh + (size_t)g * 128 + 96 + 4 * kq));

    float c = 0.0f;
    if (g < 128) hsm[g] = 0.0f;
    __syncthreads();

    float nextg = d_gpre[(size_t)t * 512 + g];   // m = 0
    const ulonglong2* wq2 = (const ulonglong2*)Wq;
    for (int m = 0; m < MM; m++) {
        float gp = nextg;
        if (m < MM - 1) nextg = d_gpre[(size_t)((m + 1) * TT + t) * 512 + g];
        unsigned long long acc = 0ull;            // packed (0,0)
        const ulonglong2* h2 = (const ulonglong2*)hsm;
        #pragma unroll
        for (int j = 0; j < 24; j++) {            // k = 0..95, register weights
            ulonglong2 hv = h2[j];
            FMA2(acc, hv.x, w[2 * j]);
            FMA2(acc, hv.y, w[2 * j + 1]);
        }
        #pragma unroll
        for (int kq = 0; kq < 8; kq++) {          // k = 96..127, smem weights
            ulonglong2 hv = h2[24 + kq];
            ulonglong2 wv = wq2[kq * 512 + g];
            FMA2(acc, hv.x, wv.x);
            FMA2(acc, hv.y, wv.y);
        }
        float lo, hi; UNPK(lo, hi, acc);
        gsm[g] = gp + lo + hi;
        __syncthreads();
        if (g < 128) {
            float ig = sigm(gsm[g]);
            float fg = sigm(gsm[128 + g]);
            float gg = tanhf(gsm[256 + g]);
            float og = sigm(gsm[384 + g]);
            c = fg * c + ig * gg;
            float hn = og * tanhf(c);
            hsm[g] = hn;
            d_lstm[(size_t)(m * TT + t) * 128 + g] = hn;
        }
        __syncthreads();
    }
}

// ---------------- fused FC1(relu)+FC2, 64 rows/block, packed f32x2 ----------------
__global__ void __launch_bounds__(256)
k_fc(const float* __restrict__ fc1w, const float* __restrict__ fc1b,
     const float* __restrict__ fc2w, const float* __restrict__ fc2b,
     float* __restrict__ out) {
    extern __shared__ float sm[];
    float* w1t = sm;                   // [64][130]  fc1w transposed [c][k]
    float* w2t = w1t + 64 * 130;       // [32][66]   fc2w transposed [o][k]
    float* xs  = w2t + 32 * 66;        // [64][128]
    float* mid = xs  + 64 * 128;       // [64][66]
    int tid = threadIdx.x;

    for (int i = tid; i < 128 * 64; i += 256) {
        int k = i >> 6, cc = i & 63;
        w1t[cc * 130 + k] = fc1w[i];
    }
    for (int i = tid; i < 64 * 32; i += 256) {
        int k = i >> 5, o = i & 31;
        w2t[o * 66 + k] = fc2w[i];
    }
    int rbase = blockIdx.x * 64;
    for (int i = tid; i < 64 * 32; i += 256)
        ((float4*)xs)[i] = ((const float4*)d_lstm)[(size_t)rbase * 32 + i];
    __syncthreads();

    int r = tid >> 2, q = tid & 3;
    {   // fc1: thread -> row r, cols q*16..q*16+15
        unsigned long long acc[16];
        #pragma unroll
        for (int j = 0; j < 16; j++) acc[j] = 0ull;
        const unsigned long long* xr = (const unsigned long long*)(xs + r * 128);
        #pragma unroll 4
        for (int kp = 0; kp < 64; kp++) {
            unsigned long long xv = xr[kp];
            #pragma unroll
            for (int j = 0; j < 16; j++)
                FMA2(acc[j], xv, *(const unsigned long long*)(w1t + (q * 16 + j) * 130 + 2 * kp));
        }
        #pragma unroll
        for (int j = 0; j < 16; j++) {
            float lo, hi; UNPK(lo, hi, acc[j]);
            int cc = q * 16 + j;
            mid[r * 66 + cc] = fmaxf(lo + hi + __ldg(&fc1b[cc]), 0.0f);
        }
    }
    __syncthreads();
    {   // fc2: thread -> row r, cols q*8..q*8+7
        unsigned long long acc[8];
        #pragma unroll
        for (int j = 0; j < 8; j++) acc[j] = 0ull;
        const unsigned long long* mr = (const unsigned long long*)(mid + r * 66);
        #pragma unroll 4
        for (int kp = 0; kp < 32; kp++) {
            unsigned long long mv = mr[kp];
            #pragma unroll
            for (int j = 0; j < 8; j++)
                FMA2(acc[j], mv, *(const unsigned long long*)(w2t + (q * 8 + j) * 66 + 2 * kp));
        }
        #pragma unroll
        for (int j = 0; j < 8; j++) {
            float lo, hi; UNPK(lo, hi, acc[j]);
            int o = q * 8 + j;
            out[(size_t)(rbase + r) * 32 + o] = lo + hi + __ldg(&fc2b[o]);
        }
    }
}

// ---------------- launch ----------------
extern "C" void kernel_launch(void* const* d_in, const int* in_sizes, int n_in,
                              void* d_out, int out_size) {
    const float* positions = (const float*)d_in[0];
    const float* adjacency = (const float*)d_in[1];
    const unsigned int* ego = (const unsigned int*)d_in[2];
    const float* W1   = (const float*)d_in[3];
    const float* b1   = (const float*)d_in[4];
    const float* W2   = (const float*)d_in[5];
    const float* b2   = (const float*)d_in[6];
    const float* W_ih = (const float*)d_in[7];
    const float* W_hh = (const float*)d_in[8];
    const float* b_ih = (const float*)d_in[9];
    const float* b_hh = (const float*)d_in[10];
    const float* fc1w = (const float*)d_in[11];
    const float* fc1b = (const float*)d_in[12];
    const float* fc2w = (const float*)d_in[13];
    const float* fc2b = (const float*)d_in[14];
    float* out = (float*)d_out;

    static const int GEMM_SMEM = (64 * 128 + 128 * 130) * 4;            // 99328
    static const int LSTM_SMEM = (8 * 512 * 4 + 128 + 512) * 4;         // 68096
    static const int FC_SMEM   = (64 * 130 + 32 * 66 + 64 * 128 + 64 * 66) * 4;  // 91392
    cudaFuncSetAttribute(k_gemm, cudaFuncAttributeMaxDynamicSharedMemorySize, GEMM_SMEM);
    cudaFuncSetAttribute(k_lstm, cudaFuncAttributeMaxDynamicSharedMemorySize, LSTM_SMEM);
    cudaFuncSetAttribute(k_fc,   cudaFuncAttributeMaxDynamicSharedMemorySize, FC_SMEM);

    float* bufA; cudaGetSymbolAddress((void**)&bufA, d_bufA);
    float* bufB; cudaGetSymbolAddress((void**)&bufB, d_bufB);
    float* gpre; cudaGetSymbolAddress((void**)&gpre, d_gpre);

    k_init<<<(NROWS + 255) / 256, 256>>>(ego);
    k_extract<<<dim3(8, TT), 256>>>(adjacency);
    k_z1<<<(NROWS * 128 + 255) / 256, 256>>>(positions, W1);
    k_agg<<<NROWS, 128>>>(bufA, b1, bufB, 0);                                   // h1
    k_gemm<<<dim3(625, 1), 256, GEMM_SMEM>>>(bufB, W2, bufA, 0, 0, 0, 128);     // Z2
    k_agg<<<NROWS, 128>>>(bufA, b2, bufB, 1);                                   // placeholder
    k_gemm<<<dim3(625, 4), 256, GEMM_SMEM>>>(bufB, W_ih, gpre, b_ih, b_hh, 1, 512);
    k_lstm<<<TT, 512, LSTM_SMEM>>>(W_hh);
    k_fc<<<625, 256, FC_SMEM>>>(fc1w, fc1b, fc2w, fc2b, out);
}